// round 5
// baseline (speedup 1.0000x reference)
#include <cuda_runtime.h>
#include <cstdint>
#include <cstddef>

#define NN 8192
#define KC 16
#define DD 64

// bilinear layout
#define NSEG 8                     // j segments
#define SEGJ (NN / NSEG)           // 1024 floats of j per segment
#define SEGJ4 (SEGJ / 4)           // 256 float4
#define BAND 32                    // rows per item
#define NBAND (NN / BAND)          // 256
#define NITEMS (NSEG * NBAND)      // 2048
#define GRID2 296                  // 2 blocks/SM * 148 SMs
#define TILE_FLOATS (KC * SEGJ)    // 16384 floats = 64KB

static __device__ __align__(16) float g_piT[KC][NN];   // u transposed: [k][j]
static __device__ __align__(16) float g_v[NN * KC];    // v[i][k] row-major
static __device__ float g_partials[GRID2];

// ------------------------------------------------------------------
// helpers
// ------------------------------------------------------------------
__device__ __forceinline__ unsigned long long pack2(float x, float y) {
    unsigned long long r;
    asm("mov.b64 %0, {%1, %2};" : "=l"(r) : "f"(x), "f"(y));
    return r;
}
__device__ __forceinline__ void unpack2(unsigned long long p, float& x, float& y) {
    asm("mov.b64 {%0, %1}, %2;" : "=f"(x), "=f"(y) : "l"(p));
}
__device__ __forceinline__ void fma2(unsigned long long& d, unsigned long long a,
                                     unsigned long long b) {
    asm("fma.rn.f32x2 %0, %1, %2, %0;" : "+l"(d) : "l"(a), "l"(b));
}

// ------------------------------------------------------------------
// Kernel 1: distances -> softmax pi -> write piT (u) and v
// 256 threads = 16 nodes x 16 communities; comm transposed in smem
// ------------------------------------------------------------------
__global__ void __launch_bounds__(256)
pi_kernel(const float* __restrict__ emb,    // (3, NN, DD)
          const float* __restrict__ comm,   // (KC, DD)
          const float* __restrict__ alpha_p) {
    __shared__ float cst[DD][KC];           // transposed community matrix
    const int tid  = threadIdx.x;
    const int k    = tid & 15;
    const int nloc = tid >> 4;
    const int n    = blockIdx.x * 16 + nloc;

    for (int idx = tid; idx < KC * DD; idx += 256) {
        int kk = idx >> 6;
        int d  = idx & 63;
        cst[d][kk] = comm[idx];
    }
    __syncthreads();

    const float LOR_MIN = (float)(1.0 + 1e-7);
    const float CLIP_LO = (float)(-1.0 + 1e-7);
    const float CLIP_HI = (float)(1.0 - 1e-7);

    // |c_k|^2
    float cn = 0.f;
    #pragma unroll
    for (int d = 0; d < DD; ++d) cn = fmaf(cst[d][k], cst[d][k], cn);

    float dist2;

    // ---- manifold 0: Euclidean ----
    {
        const float4* xp = reinterpret_cast<const float4*>(emb) + (size_t)n * 16;
        float dot = 0.f, xn2 = 0.f;
        #pragma unroll
        for (int q = 0; q < 16; ++q) {
            float4 x = xp[q];
            dot = fmaf(x.x, cst[4 * q + 0][k], dot);
            dot = fmaf(x.y, cst[4 * q + 1][k], dot);
            dot = fmaf(x.z, cst[4 * q + 2][k], dot);
            dot = fmaf(x.w, cst[4 * q + 3][k], dot);
            xn2 = fmaf(x.x, x.x, xn2);
            xn2 = fmaf(x.y, x.y, xn2);
            xn2 = fmaf(x.z, x.z, xn2);
            xn2 = fmaf(x.w, x.w, xn2);
        }
        dist2 = fmaxf(xn2 - 2.f * dot + cn, 0.f);
    }
    // ---- manifold 1: Lorentz (curvature -1, kk = 1) ----
    {
        const float4* xp = reinterpret_cast<const float4*>(emb) + (size_t)(NN + n) * 16;
        float dot = 0.f;
        float x0 = xp[0].x;
        #pragma unroll
        for (int q = 0; q < 16; ++q) {
            float4 x = xp[q];
            dot = fmaf(x.x, cst[4 * q + 0][k], dot);
            dot = fmaf(x.y, cst[4 * q + 1][k], dot);
            dot = fmaf(x.z, cst[4 * q + 2][k], dot);
            dot = fmaf(x.w, cst[4 * q + 3][k], dot);
        }
        float lip = dot - 2.f * x0 * cst[0][k];
        float arg = fmaxf(-lip, LOR_MIN);
        float dl  = acoshf(arg);
        dist2 = fmaf(dl, dl, dist2);
    }
    // ---- manifold 2: Sphere ----
    {
        const float4* xp = reinterpret_cast<const float4*>(emb) + (size_t)(2 * NN + n) * 16;
        float dot = 0.f;
        #pragma unroll
        for (int q = 0; q < 16; ++q) {
            float4 x = xp[q];
            dot = fmaf(x.x, cst[4 * q + 0][k], dot);
            dot = fmaf(x.y, cst[4 * q + 1][k], dot);
            dot = fmaf(x.z, cst[4 * q + 2][k], dot);
            dot = fmaf(x.w, cst[4 * q + 3][k], dot);
        }
        float cosv = fminf(fmaxf(dot, CLIP_LO), CLIP_HI);
        float ds   = acosf(cosv);
        dist2 = fmaf(ds, ds, dist2);
    }

    const float dn = sqrtf(dist2);

    // softmax across the 16 lanes sharing this node
    float m = dn;
    #pragma unroll
    for (int off = 8; off >= 1; off >>= 1)
        m = fmaxf(m, __shfl_xor_sync(0xffffffffu, m, off, 16));
    float e = expf(dn - m);
    float es = e;
    #pragma unroll
    for (int off = 8; off >= 1; off >>= 1)
        es += __shfl_xor_sync(0xffffffffu, es, off, 16);
    const float pi = e / es;
    float s = pi;
    #pragma unroll
    for (int off = 8; off >= 1; off >>= 1)
        s += __shfl_xor_sync(0xffffffffu, s, off, 16);

    const float a  = alpha_p[0];
    const float c1 = a * (1.f / ((float)KC * (float)NN));        // alpha/(K*N)
    const float c2 = 1.f / ((float)KC * (float)KC * (float)NN);  // 1/(K*K*N)

    g_piT[k][n] = pi;
    g_v[(size_t)n * KC + k] = fmaf(c1, pi, -c2 * s);
}

// ------------------------------------------------------------------
// Kernel 2: persistent blocks; warp = 4 rows x 8 k (k-split halves)
// item = (j-segment, 32-row band); tile reloaded only on segment change
// ------------------------------------------------------------------
__global__ void __launch_bounds__(256, 2)
bilinear_kernel(const float* __restrict__ R) {
    extern __shared__ __align__(16) float su[];   // [KC][SEGJ] = 64KB
    __shared__ float red[256];

    const int tid   = threadIdx.x;
    const int warp  = tid >> 5;
    const int lane  = tid & 31;
    const int rslot = warp & 3;
    const int k0    = (warp >> 2) * 8;            // 0 or 8

    const int p     = blockIdx.x;
    const int start = (p * NITEMS) / GRID2;
    const int end   = ((p + 1) * NITEMS) / GRID2;

    const ulonglong2* su2 = reinterpret_cast<const ulonglong2*>(su);
    const float4* piT4 = reinterpret_cast<const float4*>(&g_piT[0][0]);

    unsigned long long acc0 = 0, acc1 = 0, acc2 = 0, acc3 = 0;
    int cur_seg = -1;

    for (int item = start; item < end; ++item) {
        const int seg  = item >> 8;               // / NBAND
        const int band = item & (NBAND - 1);

        if (seg != cur_seg) {
            __syncthreads();
            #pragma unroll
            for (int r = 0; r < 16; ++r) {
                int idx = r * 256 + tid;          // 0..4095 float4s
                int kk  = idx >> 8;               // / SEGJ4
                int jj  = idx & (SEGJ4 - 1);
                reinterpret_cast<float4*>(su)[idx] =
                    piT4[(size_t)kk * (NN / 4) + (size_t)seg * SEGJ4 + jj];
            }
            __syncthreads();
            cur_seg = seg;
        }

        #pragma unroll
        for (int s = 0; s < 2; ++s) {
            const int row0 = band * BAND + s * 16 + rslot * 4;

            // v packs for this warp's 4 rows, its k-half (broadcast loads)
            unsigned long long vp[4][8];
            #pragma unroll
            for (int i = 0; i < 4; ++i) {
                const float4* vpp = reinterpret_cast<const float4*>(
                    g_v + (size_t)(row0 + i) * KC + k0);
                float4 ta = vpp[0];
                float4 tb = vpp[1];
                vp[i][0] = pack2(ta.x, ta.x);
                vp[i][1] = pack2(ta.y, ta.y);
                vp[i][2] = pack2(ta.z, ta.z);
                vp[i][3] = pack2(ta.w, ta.w);
                vp[i][4] = pack2(tb.x, tb.x);
                vp[i][5] = pack2(tb.y, tb.y);
                vp[i][6] = pack2(tb.z, tb.z);
                vp[i][7] = pack2(tb.w, tb.w);
            }

            const ulonglong2* rp0 =
                reinterpret_cast<const ulonglong2*>(R + (size_t)(row0 + 0) * NN);
            const ulonglong2* rp1 =
                reinterpret_cast<const ulonglong2*>(R + (size_t)(row0 + 1) * NN);
            const ulonglong2* rp2 =
                reinterpret_cast<const ulonglong2*>(R + (size_t)(row0 + 2) * NN);
            const ulonglong2* rp3 =
                reinterpret_cast<const ulonglong2*>(R + (size_t)(row0 + 3) * NN);

            const int gbase = seg * SEGJ4;

            #pragma unroll
            for (int it = 0; it < 8; ++it) {
                const int j4   = it * 32 + lane;  // float4 index within segment
                const int gidx = gbase + j4;      // float4 index within full row

                ulonglong2 R0 = rp0[gidx];
                ulonglong2 R1 = rp1[gidx];
                ulonglong2 R2 = rp2[gidx];
                ulonglong2 R3 = rp3[gidx];

                unsigned long long s0a = 0, s0b = 0, s1a = 0, s1b = 0;
                unsigned long long s2a = 0, s2b = 0, s3a = 0, s3b = 0;

                #pragma unroll
                for (int kk = 0; kk < 8; ++kk) {
                    ulonglong2 u = su2[(k0 + kk) * SEGJ4 + j4];
                    fma2(s0a, u.x, vp[0][kk]);
                    fma2(s0b, u.y, vp[0][kk]);
                    fma2(s1a, u.x, vp[1][kk]);
                    fma2(s1b, u.y, vp[1][kk]);
                    fma2(s2a, u.x, vp[2][kk]);
                    fma2(s2b, u.y, vp[2][kk]);
                    fma2(s3a, u.x, vp[3][kk]);
                    fma2(s3b, u.y, vp[3][kk]);
                }

                fma2(acc0, R0.x, s0a);
                fma2(acc0, R0.y, s0b);
                fma2(acc1, R1.x, s1a);
                fma2(acc1, R1.y, s1b);
                fma2(acc2, R2.x, s2a);
                fma2(acc2, R2.y, s2b);
                fma2(acc3, R3.x, s3a);
                fma2(acc3, R3.y, s3b);
            }
        }
    }

    // combine accumulator pairs (fixed order -> deterministic)
    float lo, hi, total;
    unpack2(acc0, lo, hi);
    total = lo + hi;
    unpack2(acc1, lo, hi);
    total += lo + hi;
    unpack2(acc2, lo, hi);
    total += lo + hi;
    unpack2(acc3, lo, hi);
    total += lo + hi;

    red[tid] = total;
    __syncthreads();
    #pragma unroll
    for (int off = 128; off >= 1; off >>= 1) {
        if (tid < off) red[tid] += red[tid + off];
        __syncthreads();
    }
    if (tid == 0) g_partials[p] = red[0];
}

// ------------------------------------------------------------------
// Kernel 3: finalize — sum GRID2 partials, write scalar
// ------------------------------------------------------------------
__global__ void __launch_bounds__(256)
finalize_kernel(float* __restrict__ out) {
    __shared__ float red[256];
    const int tid = threadIdx.x;
    float a = 0.f;
    for (int i = tid; i < GRID2; i += 256) a += g_partials[i];
    red[tid] = a;
    __syncthreads();
    #pragma unroll
    for (int off = 128; off >= 1; off >>= 1) {
        if (tid < off) red[tid] += red[tid + off];
        __syncthreads();
    }
    if (tid == 0) out[0] = red[0];
}

// ------------------------------------------------------------------
extern "C" void kernel_launch(void* const* d_in, const int* in_sizes, int n_in,
                              void* d_out, int out_size) {
    const float* emb   = (const float*)d_in[0];   // (3, 8192, 64)
    const float* comm  = (const float*)d_in[1];   // (16, 64)
    const float* ricci = (const float*)d_in[2];   // (8192, 8192)
    const float* alpha = (const float*)d_in[3];   // scalar
    float* out = (float*)d_out;

    cudaFuncSetAttribute(bilinear_kernel,
                         cudaFuncAttributeMaxDynamicSharedMemorySize,
                         TILE_FLOATS * (int)sizeof(float));

    pi_kernel<<<NN / 16, 256>>>(emb, comm, alpha);
    bilinear_kernel<<<GRID2, 256, TILE_FLOATS * sizeof(float)>>>(ricci);
    finalize_kernel<<<1, 256>>>(out);
}

// round 6
// speedup vs baseline: 3.8216x; 3.8216x over previous
#include <cuda_runtime.h>
#include <cstdint>
#include <cstddef>

#define NN 8192
#define KC 16
#define DD 64

#define NIC 37                      // i-chunks
#define MAXI 222                    // ceil(NN/NIC)
#define GRID2 (NIC * 8)             // 296 blocks = 2/SM * 148
#define NJG 64                      // j-groups of 128

static __device__ __align__(16) float g_piT[KC][NN];             // u: [k][j]
static __device__ __align__(16) unsigned long long g_vd[NN * KC]; // pack2(v,v)
static __device__ float g_partials[GRID2];

// ------------------------------------------------------------------
// helpers
// ------------------------------------------------------------------
__device__ __forceinline__ unsigned long long pack2(float x, float y) {
    unsigned long long r;
    asm("mov.b64 %0, {%1, %2};" : "=l"(r) : "f"(x), "f"(y));
    return r;
}
__device__ __forceinline__ void unpack2(unsigned long long p, float& x, float& y) {
    asm("mov.b64 {%0, %1}, %2;" : "=f"(x), "=f"(y) : "l"(p));
}
__device__ __forceinline__ void fma2(unsigned long long& d, unsigned long long a,
                                     unsigned long long b) {
    asm("fma.rn.f32x2 %0, %1, %2, %0;" : "+l"(d) : "l"(a), "l"(b));
}

// ------------------------------------------------------------------
// Kernel 1: distances -> softmax pi -> write piT (u) and v-dup
// 256 threads = 16 nodes x 16 communities; all 3 manifolds fused per q
// ------------------------------------------------------------------
__global__ void __launch_bounds__(256)
pi_kernel(const float* __restrict__ emb,    // (3, NN, DD)
          const float* __restrict__ comm,   // (KC, DD)
          const float* __restrict__ alpha_p) {
    __shared__ float4 c4s[DD / 4][KC];      // [q][k]
    const int tid  = threadIdx.x;
    const int k    = tid & 15;
    const int nloc = tid >> 4;
    const int n    = blockIdx.x * 16 + nloc;

    {
        const int kk = tid >> 4;
        const int q  = tid & 15;
        c4s[q][kk] = reinterpret_cast<const float4*>(comm)[kk * 16 + q];
    }
    __syncthreads();

    const float LOR_MIN = (float)(1.0 + 1e-7);
    const float CLIP_LO = (float)(-1.0 + 1e-7);
    const float CLIP_HI = (float)(1.0 - 1e-7);

    const float4* xp0 = reinterpret_cast<const float4*>(emb) + (size_t)n * 16;
    const float4* xp1 = xp0 + (size_t)NN * 16;
    const float4* xp2 = xp1 + (size_t)NN * 16;

    float dotE = 0.f, xn2 = 0.f, cn = 0.f, dotL = 0.f, dotS = 0.f;

    #pragma unroll
    for (int q = 0; q < 16; ++q) {
        float4 c = c4s[q][k];
        float4 a = xp0[q];
        float4 b = xp1[q];
        float4 d = xp2[q];
        dotE = fmaf(a.x, c.x, dotE);
        dotE = fmaf(a.y, c.y, dotE);
        dotE = fmaf(a.z, c.z, dotE);
        dotE = fmaf(a.w, c.w, dotE);
        xn2  = fmaf(a.x, a.x, xn2);
        xn2  = fmaf(a.y, a.y, xn2);
        xn2  = fmaf(a.z, a.z, xn2);
        xn2  = fmaf(a.w, a.w, xn2);
        cn   = fmaf(c.x, c.x, cn);
        cn   = fmaf(c.y, c.y, cn);
        cn   = fmaf(c.z, c.z, cn);
        cn   = fmaf(c.w, c.w, cn);
        dotL = fmaf(b.x, c.x, dotL);
        dotL = fmaf(b.y, c.y, dotL);
        dotL = fmaf(b.z, c.z, dotL);
        dotL = fmaf(b.w, c.w, dotL);
        dotS = fmaf(d.x, c.x, dotS);
        dotS = fmaf(d.y, c.y, dotS);
        dotS = fmaf(d.z, c.z, dotS);
        dotS = fmaf(d.w, c.w, dotS);
    }

    float d2 = fmaxf(xn2 - 2.f * dotE + cn, 0.f);

    const float x0  = xp1[0].x;
    const float c00 = c4s[0][k].x;
    float lip = dotL - 2.f * x0 * c00;
    float arg = fmaxf(-lip, LOR_MIN);
    float dl  = acoshf(arg);
    d2 = fmaf(dl, dl, d2);

    float cosv = fminf(fmaxf(dotS, CLIP_LO), CLIP_HI);
    float ds   = acosf(cosv);
    d2 = fmaf(ds, ds, d2);

    const float dn = sqrtf(d2);

    // softmax across the 16 lanes sharing this node
    float m = dn;
    #pragma unroll
    for (int off = 8; off >= 1; off >>= 1)
        m = fmaxf(m, __shfl_xor_sync(0xffffffffu, m, off, 16));
    float e = expf(dn - m);
    float es = e;
    #pragma unroll
    for (int off = 8; off >= 1; off >>= 1)
        es += __shfl_xor_sync(0xffffffffu, es, off, 16);
    const float pi = e / es;
    float s = pi;
    #pragma unroll
    for (int off = 8; off >= 1; off >>= 1)
        s += __shfl_xor_sync(0xffffffffu, s, off, 16);

    const float a  = alpha_p[0];
    const float c1 = a * (1.f / ((float)KC * (float)NN));        // alpha/(K*N)
    const float c2 = 1.f / ((float)KC * (float)KC * (float)NN);  // 1/(K*K*N)
    const float vv = fmaf(c1, pi, -c2 * s);

    g_piT[k][n] = pi;
    g_vd[(size_t)n * KC + k] = pack2(vv, vv);
}

// ------------------------------------------------------------------
// Kernel 2: warp owns 128 j's (u in regs); block owns one i-chunk
// (v-dup staged in smem once). R streamed exactly once, prefetch depth 1.
// ------------------------------------------------------------------
__global__ void __launch_bounds__(256)
bilinear_kernel(const float* __restrict__ R) {
    __shared__ __align__(16) unsigned long long svd[MAXI * KC];  // 28.4KB
    __shared__ float red[256];

    const int tid  = threadIdx.x;
    const int warp = tid >> 5;
    const int lane = tid & 31;
    const int b    = blockIdx.x;
    const int ic   = b >> 3;                       // 0..36 (same for all warps)
    const int jg   = (b & 7) * 8 + warp;           // 0..63
    const int jbase = jg * 128 + lane * 4;

    const int i0 = (ic * NN) / NIC;
    const int i1 = ((ic + 1) * NN) / NIC;
    const int nrows = i1 - i0;

    // stage v-dup chunk into smem (coalesced)
    {
        const ulonglong2* src =
            reinterpret_cast<const ulonglong2*>(g_vd + (size_t)i0 * KC);
        ulonglong2* dst = reinterpret_cast<ulonglong2*>(svd);
        const int cnt = nrows * (KC / 2);          // <= 1776
        for (int idx = tid; idx < cnt; idx += 256) dst[idx] = src[idx];
    }

    // u for this warp's 4 j's, all 16 k -> registers (j-packed pairs)
    ulonglong2 u[KC];
    #pragma unroll
    for (int k = 0; k < KC; ++k)
        u[k] = *reinterpret_cast<const ulonglong2*>(&g_piT[k][jbase]);

    __syncthreads();

    unsigned long long acc_a = 0, acc_b = 0;

    const char* Rrow = reinterpret_cast<const char*>(R + (size_t)i0 * NN + jbase);
    const size_t rstride = (size_t)NN * sizeof(float);

    ulonglong2 Rv = *reinterpret_cast<const ulonglong2*>(Rrow);

    for (int r = 0; r < nrows; ++r) {
        // prefetch next row's R (clamped to stay in-bounds on last iter)
        const char* nxt = Rrow + ((r + 1 < nrows) ? rstride : 0);
        ulonglong2 Rn = *reinterpret_cast<const ulonglong2*>(nxt);

        const ulonglong2* vp =
            reinterpret_cast<const ulonglong2*>(svd + (size_t)r * KC);

        unsigned long long sa = 0, sb = 0;
        #pragma unroll
        for (int p = 0; p < 8; ++p) {
            ulonglong2 vv = vp[p];                 // {v(2p), v(2p+1)} dup-packs
            fma2(sa, u[2 * p + 0].x, vv.x);
            fma2(sb, u[2 * p + 0].y, vv.x);
            fma2(sa, u[2 * p + 1].x, vv.y);
            fma2(sb, u[2 * p + 1].y, vv.y);
        }

        fma2(acc_a, Rv.x, sa);
        fma2(acc_b, Rv.y, sb);

        Rv = Rn;
        Rrow += rstride;
    }

    // combine pairs (fixed order -> deterministic)
    float lo, hi;
    unpack2(acc_a, lo, hi);
    float total = lo + hi;
    unpack2(acc_b, lo, hi);
    total += lo + hi;

    red[tid] = total;
    __syncthreads();
    #pragma unroll
    for (int off = 128; off >= 1; off >>= 1) {
        if (tid < off) red[tid] += red[tid + off];
        __syncthreads();
    }
    if (tid == 0) g_partials[b] = red[0];
}

// ------------------------------------------------------------------
// Kernel 3: finalize — sum GRID2 partials, write scalar
// ------------------------------------------------------------------
__global__ void __launch_bounds__(256)
finalize_kernel(float* __restrict__ out) {
    __shared__ float red[256];
    const int tid = threadIdx.x;
    float a = 0.f;
    for (int i = tid; i < GRID2; i += 256) a += g_partials[i];
    red[tid] = a;
    __syncthreads();
    #pragma unroll
    for (int off = 128; off >= 1; off >>= 1) {
        if (tid < off) red[tid] += red[tid + off];
        __syncthreads();
    }
    if (tid == 0) out[0] = red[0];
}

// ------------------------------------------------------------------
extern "C" void kernel_launch(void* const* d_in, const int* in_sizes, int n_in,
                              void* d_out, int out_size) {
    const float* emb   = (const float*)d_in[0];   // (3, 8192, 64)
    const float* comm  = (const float*)d_in[1];   // (16, 64)
    const float* ricci = (const float*)d_in[2];   // (8192, 8192)
    const float* alpha = (const float*)d_in[3];   // scalar
    float* out = (float*)d_out;

    pi_kernel<<<NN / 16, 256>>>(emb, comm, alpha);
    bilinear_kernel<<<GRID2, 256>>>(ricci);
    finalize_kernel<<<1, 256>>>(out);
}

// round 7
// speedup vs baseline: 4.6080x; 1.2058x over previous
#include <cuda_runtime.h>
#include <cstdint>
#include <cstddef>

#define NN 8192
#define KC 16
#define DD 64

#define NIC 37                      // i-chunks
#define MAXI 222                    // max rows per chunk
#define PADI 224                    // MAXI rounded to 4
#define GRID2 (NIC * 8)             // 296 blocks = 2/SM * 148

static __device__ __align__(16) float g_piT[KC][NN];              // u: [k][j]
static __device__ __align__(16) unsigned long long g_vd[NN * KC]; // pack2(v,v)
static __device__ float g_partials[GRID2];

// ------------------------------------------------------------------
// helpers
// ------------------------------------------------------------------
__device__ __forceinline__ unsigned long long pack2(float x, float y) {
    unsigned long long r;
    asm("mov.b64 %0, {%1, %2};" : "=l"(r) : "f"(x), "f"(y));
    return r;
}
__device__ __forceinline__ void unpack2(unsigned long long p, float& x, float& y) {
    asm("mov.b64 {%0, %1}, %2;" : "=f"(x), "=f"(y) : "l"(p));
}
__device__ __forceinline__ void fma2(unsigned long long& d, unsigned long long a,
                                     unsigned long long b) {
    asm("fma.rn.f32x2 %0, %1, %2, %0;" : "+l"(d) : "l"(a), "l"(b));
}

// ------------------------------------------------------------------
// Kernel 1: distances -> softmax pi -> write piT (u) and v-dup
// 256 threads = 16 k-lanes x 16 node-slots, 2 nodes per thread (ILP)
// note: sum_k softmax = 1 exactly, so v = c1*pi - c2 (no 3rd reduction)
// ------------------------------------------------------------------
__global__ void __launch_bounds__(256)
pi_kernel(const float* __restrict__ emb,    // (3, NN, DD)
          const float* __restrict__ comm,   // (KC, DD)
          const float* __restrict__ alpha_p) {
    __shared__ float4 c4s[DD / 4][KC];      // [q][k]
    const int tid  = threadIdx.x;
    const int k    = tid & 15;
    const int nloc = tid >> 4;
    const int n0   = blockIdx.x * 32 + nloc;
    const int n1   = n0 + 16;

    {
        const int kk = tid >> 4;
        const int q  = tid & 15;
        c4s[q][kk] = reinterpret_cast<const float4*>(comm)[kk * 16 + q];
    }
    __syncthreads();

    const float LOR_MIN = (float)(1.0 + 1e-7);
    const float CLIP_LO = (float)(-1.0 + 1e-7);
    const float CLIP_HI = (float)(1.0 - 1e-7);

    const float4* A0 = reinterpret_cast<const float4*>(emb) + (size_t)n0 * 16;
    const float4* B0 = A0 + (size_t)NN * 16;
    const float4* C0 = B0 + (size_t)NN * 16;
    const float4* A1 = reinterpret_cast<const float4*>(emb) + (size_t)n1 * 16;
    const float4* B1 = A1 + (size_t)NN * 16;
    const float4* C1 = B1 + (size_t)NN * 16;

    float dE0 = 0.f, xn0 = 0.f, dL0 = 0.f, dS0 = 0.f;
    float dE1 = 0.f, xn1 = 0.f, dL1 = 0.f, dS1 = 0.f;
    float cn = 0.f;

    #pragma unroll
    for (int q = 0; q < 16; ++q) {
        float4 c = c4s[q][k];
        cn = fmaf(c.x, c.x, cn);
        cn = fmaf(c.y, c.y, cn);
        cn = fmaf(c.z, c.z, cn);
        cn = fmaf(c.w, c.w, cn);

        float4 a = A0[q];
        dE0 = fmaf(a.x, c.x, dE0); dE0 = fmaf(a.y, c.y, dE0);
        dE0 = fmaf(a.z, c.z, dE0); dE0 = fmaf(a.w, c.w, dE0);
        xn0 = fmaf(a.x, a.x, xn0); xn0 = fmaf(a.y, a.y, xn0);
        xn0 = fmaf(a.z, a.z, xn0); xn0 = fmaf(a.w, a.w, xn0);
        float4 b = B0[q];
        dL0 = fmaf(b.x, c.x, dL0); dL0 = fmaf(b.y, c.y, dL0);
        dL0 = fmaf(b.z, c.z, dL0); dL0 = fmaf(b.w, c.w, dL0);
        float4 d = C0[q];
        dS0 = fmaf(d.x, c.x, dS0); dS0 = fmaf(d.y, c.y, dS0);
        dS0 = fmaf(d.z, c.z, dS0); dS0 = fmaf(d.w, c.w, dS0);

        float4 a1 = A1[q];
        dE1 = fmaf(a1.x, c.x, dE1); dE1 = fmaf(a1.y, c.y, dE1);
        dE1 = fmaf(a1.z, c.z, dE1); dE1 = fmaf(a1.w, c.w, dE1);
        xn1 = fmaf(a1.x, a1.x, xn1); xn1 = fmaf(a1.y, a1.y, xn1);
        xn1 = fmaf(a1.z, a1.z, xn1); xn1 = fmaf(a1.w, a1.w, xn1);
        float4 b1 = B1[q];
        dL1 = fmaf(b1.x, c.x, dL1); dL1 = fmaf(b1.y, c.y, dL1);
        dL1 = fmaf(b1.z, c.z, dL1); dL1 = fmaf(b1.w, c.w, dL1);
        float4 d1 = C1[q];
        dS1 = fmaf(d1.x, c.x, dS1); dS1 = fmaf(d1.y, c.y, dS1);
        dS1 = fmaf(d1.z, c.z, dS1); dS1 = fmaf(d1.w, c.w, dS1);
    }

    const float c00 = c4s[0][k].x;

    float d2_0 = fmaxf(xn0 - 2.f * dE0 + cn, 0.f);
    float d2_1 = fmaxf(xn1 - 2.f * dE1 + cn, 0.f);

    float lip0 = dL0 - 2.f * B0[0].x * c00;
    float lip1 = dL1 - 2.f * B1[0].x * c00;
    float dl0 = acoshf(fmaxf(-lip0, LOR_MIN));
    float dl1 = acoshf(fmaxf(-lip1, LOR_MIN));
    d2_0 = fmaf(dl0, dl0, d2_0);
    d2_1 = fmaf(dl1, dl1, d2_1);

    float ds0 = acosf(fminf(fmaxf(dS0, CLIP_LO), CLIP_HI));
    float ds1 = acosf(fminf(fmaxf(dS1, CLIP_LO), CLIP_HI));
    d2_0 = fmaf(ds0, ds0, d2_0);
    d2_1 = fmaf(ds1, ds1, d2_1);

    const float dn0 = sqrtf(d2_0);
    const float dn1 = sqrtf(d2_1);

    // softmax across the 16 lanes sharing each node (two independent chains)
    float m0 = dn0, m1 = dn1;
    #pragma unroll
    for (int off = 8; off >= 1; off >>= 1) {
        m0 = fmaxf(m0, __shfl_xor_sync(0xffffffffu, m0, off, 16));
        m1 = fmaxf(m1, __shfl_xor_sync(0xffffffffu, m1, off, 16));
    }
    float e0 = expf(dn0 - m0);
    float e1 = expf(dn1 - m1);
    float es0 = e0, es1 = e1;
    #pragma unroll
    for (int off = 8; off >= 1; off >>= 1) {
        es0 += __shfl_xor_sync(0xffffffffu, es0, off, 16);
        es1 += __shfl_xor_sync(0xffffffffu, es1, off, 16);
    }
    const float pi0 = e0 / es0;
    const float pi1 = e1 / es1;

    const float a  = alpha_p[0];
    const float c1 = a * (1.f / ((float)KC * (float)NN));        // alpha/(K*N)
    const float c2 = 1.f / ((float)KC * (float)KC * (float)NN);  // 1/(K*K*N), s==1
    const float v0 = fmaf(c1, pi0, -c2);
    const float v1 = fmaf(c1, pi1, -c2);

    g_piT[k][n0] = pi0;
    g_piT[k][n1] = pi1;
    g_vd[(size_t)n0 * KC + k] = pack2(v0, v0);
    g_vd[(size_t)n1 * KC + k] = pack2(v1, v1);
}

// ------------------------------------------------------------------
// Kernel 2: warp owns 128 j's (u in regs); block owns one i-chunk.
// R streamed once; 4-deep rolling register prefetch (MLP=4).
// ------------------------------------------------------------------
__global__ void __launch_bounds__(256, 2)
bilinear_kernel(const float* __restrict__ R) {
    __shared__ __align__(16) unsigned long long svd[PADI * KC];  // 28KB
    __shared__ float red[256];

    const int tid  = threadIdx.x;
    const int warp = tid >> 5;
    const int lane = tid & 31;
    const int b    = blockIdx.x;
    const int ic   = b >> 3;                       // 0..36
    const int jg   = (b & 7) * 8 + warp;           // 0..63
    const int jbase = jg * 128 + lane * 4;

    const int i0 = (ic * NN) / NIC;
    const int i1 = ((ic + 1) * NN) / NIC;
    const int nrows = i1 - i0;
    const int nr4 = (nrows + 3) & ~3;

    // stage v-dup chunk into smem; zero-pad rows [nrows, PADI)
    {
        const ulonglong2* src =
            reinterpret_cast<const ulonglong2*>(g_vd + (size_t)i0 * KC);
        ulonglong2* dst = reinterpret_cast<ulonglong2*>(svd);
        const int cnt = nrows * (KC / 2);
        for (int idx = tid; idx < cnt; idx += 256) dst[idx] = src[idx];
        for (int idx = cnt + tid; idx < PADI * (KC / 2); idx += 256)
            dst[idx] = make_ulonglong2(0ull, 0ull);
    }

    // u for this warp's 4 j's, all 16 k (j-packed pairs) -> 64 regs
    ulonglong2 u[KC];
    #pragma unroll
    for (int k = 0; k < KC; ++k)
        u[k] = *reinterpret_cast<const ulonglong2*>(&g_piT[k][jbase]);

    __syncthreads();

    const char* Rbase = reinterpret_cast<const char*>(R + (size_t)i0 * NN + jbase);
    const size_t rstride = (size_t)NN * sizeof(float);
    const int rmax = nrows - 1;

    unsigned long long acc_a = 0, acc_b = 0;

    #define RADDR(rr) reinterpret_cast<const ulonglong2*>( \
        Rbase + (size_t)min((rr), rmax) * rstride)

    ulonglong2 Rb0 = *RADDR(0);
    ulonglong2 Rb1 = *RADDR(1);
    ulonglong2 Rb2 = *RADDR(2);
    ulonglong2 Rb3 = *RADDR(3);

    #define ROWSTEP(RV, rr) do {                                          \
        const ulonglong2* vp =                                            \
            reinterpret_cast<const ulonglong2*>(svd + (size_t)(rr) * KC); \
        unsigned long long sa = 0, sb = 0;                                \
        _Pragma("unroll")                                                 \
        for (int p = 0; p < 8; ++p) {                                     \
            ulonglong2 vv = vp[p];                                        \
            fma2(sa, u[2 * p + 0].x, vv.x);                               \
            fma2(sb, u[2 * p + 0].y, vv.x);                               \
            fma2(sa, u[2 * p + 1].x, vv.y);                               \
            fma2(sb, u[2 * p + 1].y, vv.y);                               \
        }                                                                 \
        fma2(acc_a, (RV).x, sa);                                          \
        fma2(acc_b, (RV).y, sb);                                          \
    } while (0)

    for (int rb = 0; rb < nr4; rb += 4) {
        ulonglong2 R0 = Rb0; Rb0 = *RADDR(rb + 4);
        ulonglong2 R1 = Rb1; Rb1 = *RADDR(rb + 5);
        ulonglong2 R2 = Rb2; Rb2 = *RADDR(rb + 6);
        ulonglong2 R3 = Rb3; Rb3 = *RADDR(rb + 7);
        ROWSTEP(R0, rb + 0);
        ROWSTEP(R1, rb + 1);
        ROWSTEP(R2, rb + 2);
        ROWSTEP(R3, rb + 3);
    }

    #undef ROWSTEP
    #undef RADDR

    // combine pairs (fixed order -> deterministic)
    float lo, hi;
    unpack2(acc_a, lo, hi);
    float total = lo + hi;
    unpack2(acc_b, lo, hi);
    total += lo + hi;

    red[tid] = total;
    __syncthreads();
    #pragma unroll
    for (int off = 128; off >= 1; off >>= 1) {
        if (tid < off) red[tid] += red[tid + off];
        __syncthreads();
    }
    if (tid == 0) g_partials[b] = red[0];
}

// ------------------------------------------------------------------
// Kernel 3: finalize — sum GRID2 partials, write scalar
// ------------------------------------------------------------------
__global__ void __launch_bounds__(256)
finalize_kernel(float* __restrict__ out) {
    __shared__ float red[256];
    const int tid = threadIdx.x;
    float a = 0.f;
    for (int i = tid; i < GRID2; i += 256) a += g_partials[i];
    red[tid] = a;
    __syncthreads();
    #pragma unroll
    for (int off = 128; off >= 1; off >>= 1) {
        if (tid < off) red[tid] += red[tid + off];
        __syncthreads();
    }
    if (tid == 0) out[0] = red[0];
}

// ------------------------------------------------------------------
extern "C" void kernel_launch(void* const* d_in, const int* in_sizes, int n_in,
                              void* d_out, int out_size) {
    const float* emb   = (const float*)d_in[0];   // (3, 8192, 64)
    const float* comm  = (const float*)d_in[1];   // (16, 64)
    const float* ricci = (const float*)d_in[2];   // (8192, 8192)
    const float* alpha = (const float*)d_in[3];   // scalar
    float* out = (float*)d_out;

    pi_kernel<<<NN / 32, 256>>>(emb, comm, alpha);
    bilinear_kernel<<<GRID2, 256>>>(ricci);
    finalize_kernel<<<1, 256>>>(out);
}